// round 5
// baseline (speedup 1.0000x reference)
#include <cuda_runtime.h>

// RC Backward-Euler 2x2 recurrence as a blocked affine scan.
// x_{k+1} = P_k x_k + q_k. Per-element maps in fp32; all cross-segment
// composition in fp64. All reductions/scans preserve sequential order
// (affine composition is non-commutative).

#define SEG 32
#define TPB 256
#define EPB (SEG * TPB)      // 8192 elements per block
#define MAX_SEGS (1 << 19)
#define MAX_BLKS 2048
#define K2_T 512

struct Aff  { float  a11, a12, a21, a22, b0, b1; };
struct AffD { double a11, a12, a21, a22, b0, b1; };

__device__ float  g_seg[6 * MAX_SEGS];
__device__ double g_blk[6 * MAX_BLKS];
__device__ double g_bst[2 * MAX_BLKS];

__device__ __forceinline__ Aff aff_identity() {
    Aff r; r.a11 = 1.f; r.a12 = 0.f; r.a21 = 0.f; r.a22 = 1.f; r.b0 = 0.f; r.b1 = 0.f;
    return r;
}
__device__ __forceinline__ AffD affd_identity() {
    AffD r; r.a11 = 1.; r.a12 = 0.; r.a21 = 0.; r.a22 = 1.; r.b0 = 0.; r.b1 = 0.;
    return r;
}
// result = apply e (earlier), then l (later):  L*E matrix product, b = L*e.b + l.b
__device__ __forceinline__ Aff compose(const Aff& e, const Aff& l) {
    Aff r;
    r.a11 = l.a11 * e.a11 + l.a12 * e.a21;
    r.a12 = l.a11 * e.a12 + l.a12 * e.a22;
    r.a21 = l.a21 * e.a11 + l.a22 * e.a21;
    r.a22 = l.a21 * e.a12 + l.a22 * e.a22;
    r.b0  = l.a11 * e.b0  + l.a12 * e.b1 + l.b0;
    r.b1  = l.a21 * e.b0  + l.a22 * e.b1 + l.b1;
    return r;
}
__device__ __forceinline__ AffD composeD(const AffD& e, const AffD& l) {
    AffD r;
    r.a11 = l.a11 * e.a11 + l.a12 * e.a21;
    r.a12 = l.a11 * e.a12 + l.a12 * e.a22;
    r.a21 = l.a21 * e.a11 + l.a22 * e.a21;
    r.a22 = l.a21 * e.a12 + l.a22 * e.a22;
    r.b0  = l.a11 * e.b0  + l.a12 * e.b1 + l.b0;
    r.b1  = l.a21 * e.b0  + l.a22 * e.b1 + l.b1;
    return r;
}
__device__ __forceinline__ AffD toD(const Aff& a) {
    AffD r; r.a11 = a.a11; r.a12 = a.a12; r.a21 = a.a21; r.a22 = a.a22;
    r.b0 = a.b0; r.b1 = a.b1; return r;
}

struct Consts {
    float M11, M12, M21, M12M21;
    float invRie;
    float Cin, CenRea;
    float cs0, ci0;
    float cs1, ci1;
};

__device__ __forceinline__ Consts make_consts(
    const float* R_ie, const float* R_ea, const float* C_in, const float* C_en,
    const float* a_sol_in, const float* a_sol_en,
    const float* a_int_in, const float* a_int_en)
{
    const float dt = 1800.0f;
    float rie = *R_ie, rea = *R_ea, cin = *C_in, cen = *C_en;
    float invRie = 1.0f / rie;
    float invRea = 1.0f / rea;
    Consts c;
    c.invRie = invRie;
    c.Cin    = cin;
    c.CenRea = __fmul_rn(cen, rea);
    float A11 = -(__fadd_rn(invRea, invRie) / cen);
    c.M11 = __fsub_rn(1.0f, __fmul_rn(dt, A11));
    float A12 = invRie / cen;
    c.M12 = -__fmul_rn(dt, A12);
    float A21 = invRie / cin;
    c.M21 = -__fmul_rn(dt, A21);
    c.M12M21 = __fmul_rn(c.M12, c.M21);
    c.cs0 = (*a_sol_en) / cen;
    c.ci0 = (*a_int_en) / cen;
    c.cs1 = (*a_sol_in) / cin;
    c.ci1 = (*a_int_in) / cin;
    return c;
}

__device__ __forceinline__ void elem_core(
    const Consts& c, float To, float Irr, float Qint, float Qah, float Ria,
    float& M22, float& det, float& bu0, float& bu1)
{
    const float dt = 1800.0f;
    float Ria_c  = fmaxf(Ria, 1e-6f);
    float invRia = 1.0f / Ria_c;
    float A22 = -(__fadd_rn(invRia, c.invRie) / c.Cin);
    M22 = __fsub_rn(1.0f, __fmul_rn(dt, A22));
    det = __fsub_rn(__fmul_rn(c.M11, M22), c.M12M21);
    float qsol = 31.388f * Irr;
    bu0 = dt * ((To / c.CenRea + c.cs0 * qsol) + c.ci0 * Qint);
    float d1 = __fmul_rn(c.Cin, Ria_c);
    bu1 = dt * (((To / d1 + c.cs1 * qsol) + c.ci1 * Qint) + Qah / c.Cin);
}

__device__ __forceinline__ Aff elem_map(
    const Consts& c, float To, float Irr, float Qint, float Qah, float Ria)
{
    float M22, det, bu0, bu1;
    elem_core(c, To, Irr, Qint, Qah, Ria, M22, det, bu0, bu1);
    float invdet = 1.0f / det;
    Aff p;
    p.a11 =  M22   * invdet;
    p.a12 = -c.M12 * invdet;
    p.a21 = -c.M21 * invdet;
    p.a22 =  c.M11 * invdet;
    p.b0  = p.a11 * bu0 + p.a12 * bu1;
    p.b1  = p.a21 * bu0 + p.a22 * bu1;
    return p;
}

// ---------------- K1: per-segment maps + ORDERED per-block reduce ----------
__global__ void __launch_bounds__(TPB)
k1_segmaps(const float* __restrict__ To, const float* __restrict__ Irr,
           const float* __restrict__ Qint, const float* __restrict__ Qah,
           const float* __restrict__ Ria,
           const float* R_ie, const float* R_ea, const float* C_in, const float* C_en,
           const float* a_sol_in, const float* a_sol_en,
           const float* a_int_in, const float* a_int_en,
           int N)
{
    Consts c = make_consts(R_ie, R_ea, C_in, C_en, a_sol_in, a_sol_en, a_int_in, a_int_en);
    int g = blockIdx.x * TPB + threadIdx.x;
    long base = (long)g * SEG;
    Aff acc = aff_identity();

    if (base + SEG <= (long)N) {
        const float4* To4 = (const float4*)To;
        const float4* Ir4 = (const float4*)Irr;
        const float4* Qi4 = (const float4*)Qint;
        const float4* Qa4 = (const float4*)Qah;
        const float4* Ra4 = (const float4*)Ria;
        int v = g * (SEG / 4);
        #pragma unroll
        for (int j = 0; j < SEG / 4; j++) {
            float4 ft = To4[v + j], fi = Ir4[v + j], fq = Qi4[v + j];
            float4 fa = Qa4[v + j], fr = Ra4[v + j];
            float tv[4] = {ft.x, ft.y, ft.z, ft.w};
            float iv[4] = {fi.x, fi.y, fi.z, fi.w};
            float qv[4] = {fq.x, fq.y, fq.z, fq.w};
            float av[4] = {fa.x, fa.y, fa.z, fa.w};
            float rv[4] = {fr.x, fr.y, fr.z, fr.w};
            #pragma unroll
            for (int e = 0; e < 4; e++) {
                Aff p = elem_map(c, tv[e], iv[e], qv[e], av[e], rv[e]);
                acc = compose(acc, p);
            }
        }
    } else if (base < (long)N) {
        for (long k = base; k < (long)N && k < base + SEG; k++) {
            Aff p = elem_map(c, To[k], Irr[k], Qint[k], Qah[k], Ria[k]);
            acc = compose(acc, p);
        }
    }

    g_seg[0 * MAX_SEGS + g] = acc.a11;
    g_seg[1 * MAX_SEGS + g] = acc.a12;
    g_seg[2 * MAX_SEGS + g] = acc.a21;
    g_seg[3 * MAX_SEGS + g] = acc.a22;
    g_seg[4 * MAX_SEGS + g] = acc.b0;
    g_seg[5 * MAX_SEGS + g] = acc.b1;

    // ORDER-CORRECT block reduction in fp64: contiguous-pair tree.
    // sm[t] covers [t, t+off); merge with sm[t+off] covering [t+off, t+2*off):
    // compose(earlier=sm[t], later=sm[t+off]).
    __shared__ AffD sm[TPB];
    sm[threadIdx.x] = toD(acc);
    __syncthreads();
    #pragma unroll
    for (int off = 1; off < TPB; off <<= 1) {
        if ((threadIdx.x & (2 * off - 1)) == 0)
            sm[threadIdx.x] = composeD(sm[threadIdx.x], sm[threadIdx.x + off]);
        __syncthreads();
    }
    if (threadIdx.x == 0) {
        AffD b = sm[0];
        g_blk[0 * MAX_BLKS + blockIdx.x] = b.a11;
        g_blk[1 * MAX_BLKS + blockIdx.x] = b.a12;
        g_blk[2 * MAX_BLKS + blockIdx.x] = b.a21;
        g_blk[3 * MAX_BLKS + blockIdx.x] = b.a22;
        g_blk[4 * MAX_BLKS + blockIdx.x] = b.b0;
        g_blk[5 * MAX_BLKS + blockIdx.x] = b.b1;
    }
}

// ---------------- K2: fp64 Hillis-Steele scan of block maps ----------------
__global__ void __launch_bounds__(K2_T)
k2_blockscan(const float* Tin0p, int nblk)
{
    double t0 = (double)(*Tin0p);

    if (nblk > K2_T) {            // serial fallback (not hit at N=4M)
        if (threadIdx.x == 0) {
            double x0 = t0, x1 = t0;
            for (int i = 0; i < nblk; i++) {
                g_bst[2 * i] = x0; g_bst[2 * i + 1] = x1;
                double a11 = g_blk[0 * MAX_BLKS + i], a12 = g_blk[1 * MAX_BLKS + i];
                double a21 = g_blk[2 * MAX_BLKS + i], a22 = g_blk[3 * MAX_BLKS + i];
                double b0  = g_blk[4 * MAX_BLKS + i], b1  = g_blk[5 * MAX_BLKS + i];
                double y0 = a11 * x0 + a12 * x1 + b0;
                double y1 = a21 * x0 + a22 * x1 + b1;
                x0 = y0; x1 = y1;
            }
        }
        return;
    }

    __shared__ AffD sm[K2_T];
    int i = threadIdx.x;
    AffD v = affd_identity();
    if (i < nblk) {
        v.a11 = g_blk[0 * MAX_BLKS + i]; v.a12 = g_blk[1 * MAX_BLKS + i];
        v.a21 = g_blk[2 * MAX_BLKS + i]; v.a22 = g_blk[3 * MAX_BLKS + i];
        v.b0  = g_blk[4 * MAX_BLKS + i]; v.b1  = g_blk[5 * MAX_BLKS + i];
    }
    sm[i] = v;
    __syncthreads();
    for (int st = 1; st < nblk; st <<= 1) {
        AffD add;
        bool has = (i >= st);
        if (has) add = sm[i - st];
        __syncthreads();
        if (has) v = composeD(add, v);
        sm[i] = v;
        __syncthreads();
    }
    if (i < nblk) {
        double x0 = t0, x1 = t0;
        if (i > 0) {
            AffD e = sm[i - 1];
            double y0 = e.a11 * x0 + e.a12 * x1 + e.b0;
            double y1 = e.a21 * x0 + e.a22 * x1 + e.b1;
            x0 = y0; x1 = y1;
        }
        g_bst[2 * i] = x0; g_bst[2 * i + 1] = x1;
    }
}

// ---------------- K3: fp64 intra-block scan + fp32 replay ------------------
__global__ void __launch_bounds__(TPB)
k3_replay(const float* __restrict__ To, const float* __restrict__ Irr,
          const float* __restrict__ Qint, const float* __restrict__ Qah,
          const float* __restrict__ Ria,
          const float* R_ie, const float* R_ea, const float* C_in, const float* C_en,
          const float* a_sol_in, const float* a_sol_en,
          const float* a_int_in, const float* a_int_en,
          float* __restrict__ out, int N)
{
    Consts c = make_consts(R_ie, R_ea, C_in, C_en, a_sol_in, a_sol_en, a_int_in, a_int_en);
    int g = blockIdx.x * TPB + threadIdx.x;
    int i = threadIdx.x;

    Aff myf;
    myf.a11 = g_seg[0 * MAX_SEGS + g]; myf.a12 = g_seg[1 * MAX_SEGS + g];
    myf.a21 = g_seg[2 * MAX_SEGS + g]; myf.a22 = g_seg[3 * MAX_SEGS + g];
    myf.b0  = g_seg[4 * MAX_SEGS + g]; myf.b1  = g_seg[5 * MAX_SEGS + g];

    __shared__ AffD sm[TPB];
    AffD v = toD(myf);
    sm[i] = v;
    __syncthreads();
    #pragma unroll
    for (int st = 1; st < TPB; st <<= 1) {
        AffD add;
        bool has = (i >= st);
        if (has) add = sm[i - st];
        __syncthreads();
        if (has) v = composeD(add, v);
        sm[i] = v;
        __syncthreads();
    }

    double bs0 = g_bst[2 * blockIdx.x], bs1 = g_bst[2 * blockIdx.x + 1];
    double dx0, dx1;
    if (i == 0) { dx0 = bs0; dx1 = bs1; }
    else {
        AffD e = sm[i - 1];
        dx0 = e.a11 * bs0 + e.a12 * bs1 + e.b0;
        dx1 = e.a21 * bs0 + e.a22 * bs1 + e.b1;
    }
    float x0 = (float)dx0, x1 = (float)dx1;

    long base = (long)g * SEG;
    if (base + SEG <= (long)N) {
        const float4* To4 = (const float4*)To;
        const float4* Ir4 = (const float4*)Irr;
        const float4* Qi4 = (const float4*)Qint;
        const float4* Qa4 = (const float4*)Qah;
        const float4* Ra4 = (const float4*)Ria;
        float4* Out4 = (float4*)out;
        int vbase = g * (SEG / 4);
        #pragma unroll
        for (int j = 0; j < SEG / 4; j++) {
            float4 ft = To4[vbase + j], fi = Ir4[vbase + j], fq = Qi4[vbase + j];
            float4 fa = Qa4[vbase + j], fr = Ra4[vbase + j];
            float tv[4] = {ft.x, ft.y, ft.z, ft.w};
            float iv[4] = {fi.x, fi.y, fi.z, fi.w};
            float qv[4] = {fq.x, fq.y, fq.z, fq.w};
            float av[4] = {fa.x, fa.y, fa.z, fa.w};
            float rv[4] = {fr.x, fr.y, fr.z, fr.w};
            float ov[4];
            #pragma unroll
            for (int e = 0; e < 4; e++) {
                float M22, det, bu0, bu1;
                elem_core(c, tv[e], iv[e], qv[e], av[e], rv[e], M22, det, bu0, bu1);
                float r0 = x0 + bu0;
                float r1 = x1 + bu1;
                float n0 = __fsub_rn(__fmul_rn(M22,   r0), __fmul_rn(c.M12, r1));
                float n1 = __fsub_rn(__fmul_rn(c.M11, r1), __fmul_rn(c.M21, r0));
                x0 = n0 / det;
                x1 = n1 / det;
                ov[e] = x1;
            }
            Out4[vbase + j] = make_float4(ov[0], ov[1], ov[2], ov[3]);
        }
    } else if (base < (long)N) {
        for (long k = base; k < (long)N && k < base + SEG; k++) {
            float M22, det, bu0, bu1;
            elem_core(c, To[k], Irr[k], Qint[k], Qah[k], Ria[k], M22, det, bu0, bu1);
            float r0 = x0 + bu0;
            float r1 = x1 + bu1;
            float n0 = __fsub_rn(__fmul_rn(M22,   r0), __fmul_rn(c.M12, r1));
            float n1 = __fsub_rn(__fmul_rn(c.M11, r1), __fmul_rn(c.M21, r0));
            x0 = n0 / det;
            x1 = n1 / det;
            out[k] = x1;
        }
    }
}

extern "C" void kernel_launch(void* const* d_in, const int* in_sizes, int n_in,
                              void* d_out, int out_size)
{
    const float* R_ie    = (const float*)d_in[0];
    const float* R_ea    = (const float*)d_in[1];
    const float* C_in    = (const float*)d_in[2];
    const float* C_en    = (const float*)d_in[3];
    const float* a_sol_in = (const float*)d_in[4];
    const float* a_sol_en = (const float*)d_in[5];
    const float* a_int_in = (const float*)d_in[6];
    const float* a_int_en = (const float*)d_in[7];
    const float* Tin0    = (const float*)d_in[8];
    const float* To      = (const float*)d_in[9];
    const float* Irr     = (const float*)d_in[10];
    const float* Qint    = (const float*)d_in[11];
    const float* Qah     = (const float*)d_in[12];
    const float* Ria     = (const float*)d_in[13];
    float* out = (float*)d_out;

    int N = in_sizes[9];
    if (N <= 0) return;
    int nblk = (N + EPB - 1) / EPB;

    k1_segmaps<<<nblk, TPB>>>(To, Irr, Qint, Qah, Ria,
                              R_ie, R_ea, C_in, C_en,
                              a_sol_in, a_sol_en, a_int_in, a_int_en, N);
    k2_blockscan<<<1, K2_T>>>(Tin0, nblk);
    k3_replay<<<nblk, TPB>>>(To, Irr, Qint, Qah, Ria,
                             R_ie, R_ea, C_in, C_en,
                             a_sol_in, a_sol_en, a_int_in, a_int_en, out, N);
}

// round 7
// speedup vs baseline: 1.0883x; 1.0883x over previous
#include <cuda_runtime.h>

// RC Backward-Euler 2x2 recurrence as a blocked affine scan.
// Round 6: latency-oriented rework. SEG=16 (2x parallelism), ordered
// pairwise-tree composition in K1, division-free replay chain in K3.

#define SEG 16
#define TPB 256
#define EPB (SEG * TPB)      // 4096 elements per block
#define MAX_SEGS (1 << 19)
#define MAX_BLKS 2048
#define K2_T 1024

struct Aff  { float  a11, a12, a21, a22, b0, b1; };
struct AffD { double a11, a12, a21, a22, b0, b1; };

__device__ float  g_seg[6 * MAX_SEGS];
__device__ double g_blk[6 * MAX_BLKS];
__device__ double g_bst[2 * MAX_BLKS];

__device__ __forceinline__ Aff aff_identity() {
    Aff r; r.a11 = 1.f; r.a12 = 0.f; r.a21 = 0.f; r.a22 = 1.f; r.b0 = 0.f; r.b1 = 0.f;
    return r;
}
__device__ __forceinline__ AffD affd_identity() {
    AffD r; r.a11 = 1.; r.a12 = 0.; r.a21 = 0.; r.a22 = 1.; r.b0 = 0.; r.b1 = 0.;
    return r;
}
// result = apply e (earlier), then l (later)
__device__ __forceinline__ Aff compose(const Aff& e, const Aff& l) {
    Aff r;
    r.a11 = l.a11 * e.a11 + l.a12 * e.a21;
    r.a12 = l.a11 * e.a12 + l.a12 * e.a22;
    r.a21 = l.a21 * e.a11 + l.a22 * e.a21;
    r.a22 = l.a21 * e.a12 + l.a22 * e.a22;
    r.b0  = l.a11 * e.b0  + l.a12 * e.b1 + l.b0;
    r.b1  = l.a21 * e.b0  + l.a22 * e.b1 + l.b1;
    return r;
}
__device__ __forceinline__ AffD composeD(const AffD& e, const AffD& l) {
    AffD r;
    r.a11 = l.a11 * e.a11 + l.a12 * e.a21;
    r.a12 = l.a11 * e.a12 + l.a12 * e.a22;
    r.a21 = l.a21 * e.a11 + l.a22 * e.a21;
    r.a22 = l.a21 * e.a12 + l.a22 * e.a22;
    r.b0  = l.a11 * e.b0  + l.a12 * e.b1 + l.b0;
    r.b1  = l.a21 * e.b0  + l.a22 * e.b1 + l.b1;
    return r;
}
__device__ __forceinline__ AffD toD(const Aff& a) {
    AffD r; r.a11 = a.a11; r.a12 = a.a12; r.a21 = a.a21; r.a22 = a.a22;
    r.b0 = a.b0; r.b1 = a.b1; return r;
}

struct Consts {
    float M11, M12, M21, M12M21;
    float invRie;
    float Cin, CenRea;
    float cs0, ci0;
    float cs1, ci1;
};

__device__ __forceinline__ Consts make_consts(
    const float* R_ie, const float* R_ea, const float* C_in, const float* C_en,
    const float* a_sol_in, const float* a_sol_en,
    const float* a_int_in, const float* a_int_en)
{
    const float dt = 1800.0f;
    float rie = *R_ie, rea = *R_ea, cin = *C_in, cen = *C_en;
    float invRie = 1.0f / rie;
    float invRea = 1.0f / rea;
    Consts c;
    c.invRie = invRie;
    c.Cin    = cin;
    c.CenRea = __fmul_rn(cen, rea);
    float A11 = -(__fadd_rn(invRea, invRie) / cen);
    c.M11 = __fsub_rn(1.0f, __fmul_rn(dt, A11));
    float A12 = invRie / cen;
    c.M12 = -__fmul_rn(dt, A12);
    float A21 = invRie / cin;
    c.M21 = -__fmul_rn(dt, A21);
    c.M12M21 = __fmul_rn(c.M12, c.M21);
    c.cs0 = (*a_sol_en) / cen;
    c.ci0 = (*a_int_en) / cen;
    c.cs1 = (*a_sol_in) / cin;
    c.ci1 = (*a_int_in) / cin;
    return c;
}

// Per-element affine map x -> A x + b  (all divisions independent of any chain)
__device__ __forceinline__ Aff elem_map(
    const Consts& c, float To, float Irr, float Qint, float Qah, float Ria)
{
    const float dt = 1800.0f;
    float Ria_c  = fmaxf(Ria, 1e-6f);
    float invRia = 1.0f / Ria_c;
    float A22 = -(__fadd_rn(invRia, c.invRie) / c.Cin);
    float M22 = __fsub_rn(1.0f, __fmul_rn(dt, A22));
    float det = __fsub_rn(__fmul_rn(c.M11, M22), c.M12M21);
    float invdet = 1.0f / det;
    float qsol = 31.388f * Irr;
    float bu0 = dt * ((To / c.CenRea + c.cs0 * qsol) + c.ci0 * Qint);
    float d1  = __fmul_rn(c.Cin, Ria_c);
    float bu1 = dt * (((To / d1 + c.cs1 * qsol) + c.ci1 * Qint) + Qah / c.Cin);
    Aff p;
    p.a11 =  M22   * invdet;
    p.a12 = -c.M12 * invdet;
    p.a21 = -c.M21 * invdet;
    p.a22 =  c.M11 * invdet;
    p.b0  = p.a11 * bu0 + p.a12 * bu1;
    p.b1  = p.a21 * bu0 + p.a22 * bu1;
    return p;
}

// ---------------- K1: per-segment maps (tree-composed) + block reduce ------
__global__ void __launch_bounds__(TPB)
k1_segmaps(const float* __restrict__ To, const float* __restrict__ Irr,
           const float* __restrict__ Qint, const float* __restrict__ Qah,
           const float* __restrict__ Ria,
           const float* R_ie, const float* R_ea, const float* C_in, const float* C_en,
           const float* a_sol_in, const float* a_sol_en,
           const float* a_int_in, const float* a_int_en,
           int N)
{
    Consts c = make_consts(R_ie, R_ea, C_in, C_en, a_sol_in, a_sol_en, a_int_in, a_int_en);
    int g = blockIdx.x * TPB + threadIdx.x;
    long base = (long)g * SEG;
    Aff acc = aff_identity();

    if (base + SEG <= (long)N) {
        const float4* To4 = (const float4*)To;
        const float4* Ir4 = (const float4*)Irr;
        const float4* Qi4 = (const float4*)Qint;
        const float4* Qa4 = (const float4*)Qah;
        const float4* Ra4 = (const float4*)Ria;
        int v = g * (SEG / 4);
        #pragma unroll
        for (int j = 0; j < SEG / 4; j++) {
            float4 ft = To4[v + j], fi = Ir4[v + j], fq = Qi4[v + j];
            float4 fa = Qa4[v + j], fr = Ra4[v + j];
            // 4 independent maps, then ordered pairwise tree (contiguous)
            Aff m0 = elem_map(c, ft.x, fi.x, fq.x, fa.x, fr.x);
            Aff m1 = elem_map(c, ft.y, fi.y, fq.y, fa.y, fr.y);
            Aff m2 = elem_map(c, ft.z, fi.z, fq.z, fa.z, fr.z);
            Aff m3 = elem_map(c, ft.w, fi.w, fq.w, fa.w, fr.w);
            Aff c01 = compose(m0, m1);          // covers [0,2)
            Aff c23 = compose(m2, m3);          // covers [2,4)
            Aff gm  = compose(c01, c23);        // covers [0,4)
            acc = compose(acc, gm);
        }
    } else if (base < (long)N) {
        for (long k = base; k < (long)N && k < base + SEG; k++) {
            Aff p = elem_map(c, To[k], Irr[k], Qint[k], Qah[k], Ria[k]);
            acc = compose(acc, p);
        }
    }

    g_seg[0 * MAX_SEGS + g] = acc.a11;
    g_seg[1 * MAX_SEGS + g] = acc.a12;
    g_seg[2 * MAX_SEGS + g] = acc.a21;
    g_seg[3 * MAX_SEGS + g] = acc.a22;
    g_seg[4 * MAX_SEGS + g] = acc.b0;
    g_seg[5 * MAX_SEGS + g] = acc.b1;

    // ORDER-CORRECT contiguous-pair tree reduction in fp64
    __shared__ AffD sm[TPB];
    sm[threadIdx.x] = toD(acc);
    __syncthreads();
    #pragma unroll
    for (int off = 1; off < TPB; off <<= 1) {
        if ((threadIdx.x & (2 * off - 1)) == 0)
            sm[threadIdx.x] = composeD(sm[threadIdx.x], sm[threadIdx.x + off]);
        __syncthreads();
    }
    if (threadIdx.x == 0) {
        AffD b = sm[0];
        g_blk[0 * MAX_BLKS + blockIdx.x] = b.a11;
        g_blk[1 * MAX_BLKS + blockIdx.x] = b.a12;
        g_blk[2 * MAX_BLKS + blockIdx.x] = b.a21;
        g_blk[3 * MAX_BLKS + blockIdx.x] = b.a22;
        g_blk[4 * MAX_BLKS + blockIdx.x] = b.b0;
        g_blk[5 * MAX_BLKS + blockIdx.x] = b.b1;
    }
}

// ---------------- K2: fp64 Hillis-Steele scan of block maps ----------------
__global__ void __launch_bounds__(K2_T)
k2_blockscan(const float* Tin0p, int nblk)
{
    double t0 = (double)(*Tin0p);

    if (nblk > K2_T) {            // serial fallback (not hit at N=4M)
        if (threadIdx.x == 0) {
            double x0 = t0, x1 = t0;
            for (int i = 0; i < nblk; i++) {
                g_bst[2 * i] = x0; g_bst[2 * i + 1] = x1;
                double a11 = g_blk[0 * MAX_BLKS + i], a12 = g_blk[1 * MAX_BLKS + i];
                double a21 = g_blk[2 * MAX_BLKS + i], a22 = g_blk[3 * MAX_BLKS + i];
                double b0  = g_blk[4 * MAX_BLKS + i], b1  = g_blk[5 * MAX_BLKS + i];
                double y0 = a11 * x0 + a12 * x1 + b0;
                double y1 = a21 * x0 + a22 * x1 + b1;
                x0 = y0; x1 = y1;
            }
        }
        return;
    }

    __shared__ AffD sm[K2_T];
    int i = threadIdx.x;
    AffD v = affd_identity();
    if (i < nblk) {
        v.a11 = g_blk[0 * MAX_BLKS + i]; v.a12 = g_blk[1 * MAX_BLKS + i];
        v.a21 = g_blk[2 * MAX_BLKS + i]; v.a22 = g_blk[3 * MAX_BLKS + i];
        v.b0  = g_blk[4 * MAX_BLKS + i]; v.b1  = g_blk[5 * MAX_BLKS + i];
    }
    sm[i] = v;
    __syncthreads();
    for (int st = 1; st < nblk; st <<= 1) {
        AffD add;
        bool has = (i >= st);
        if (has) add = sm[i - st];
        __syncthreads();
        if (has) v = composeD(add, v);
        sm[i] = v;
        __syncthreads();
    }
    if (i < nblk) {
        double x0 = t0, x1 = t0;
        if (i > 0) {
            AffD e = sm[i - 1];
            double y0 = e.a11 * x0 + e.a12 * x1 + e.b0;
            double y1 = e.a21 * x0 + e.a22 * x1 + e.b1;
            x0 = y0; x1 = y1;
        }
        g_bst[2 * i] = x0; g_bst[2 * i + 1] = x1;
    }
}

// ---------------- K3: fp64 intra-block scan + division-free replay ---------
__global__ void __launch_bounds__(TPB)
k3_replay(const float* __restrict__ To, const float* __restrict__ Irr,
          const float* __restrict__ Qint, const float* __restrict__ Qah,
          const float* __restrict__ Ria,
          const float* R_ie, const float* R_ea, const float* C_in, const float* C_en,
          const float* a_sol_in, const float* a_sol_en,
          const float* a_int_in, const float* a_int_en,
          float* __restrict__ out, int N)
{
    Consts c = make_consts(R_ie, R_ea, C_in, C_en, a_sol_in, a_sol_en, a_int_in, a_int_en);
    int g = blockIdx.x * TPB + threadIdx.x;
    int i = threadIdx.x;

    Aff myf;
    myf.a11 = g_seg[0 * MAX_SEGS + g]; myf.a12 = g_seg[1 * MAX_SEGS + g];
    myf.a21 = g_seg[2 * MAX_SEGS + g]; myf.a22 = g_seg[3 * MAX_SEGS + g];
    myf.b0  = g_seg[4 * MAX_SEGS + g]; myf.b1  = g_seg[5 * MAX_SEGS + g];

    __shared__ AffD sm[TPB];
    AffD v = toD(myf);
    sm[i] = v;
    __syncthreads();
    #pragma unroll
    for (int st = 1; st < TPB; st <<= 1) {
        AffD add;
        bool has = (i >= st);
        if (has) add = sm[i - st];
        __syncthreads();
        if (has) v = composeD(add, v);
        sm[i] = v;
        __syncthreads();
    }

    double bs0 = g_bst[2 * blockIdx.x], bs1 = g_bst[2 * blockIdx.x + 1];
    double dx0, dx1;
    if (i == 0) { dx0 = bs0; dx1 = bs1; }
    else {
        AffD e = sm[i - 1];
        dx0 = e.a11 * bs0 + e.a12 * bs1 + e.b0;
        dx1 = e.a21 * bs0 + e.a22 * bs1 + e.b1;
    }
    float x0 = (float)dx0, x1 = (float)dx1;

    long base = (long)g * SEG;
    if (base + SEG <= (long)N) {
        const float4* To4 = (const float4*)To;
        const float4* Ir4 = (const float4*)Irr;
        const float4* Qi4 = (const float4*)Qint;
        const float4* Qa4 = (const float4*)Qah;
        const float4* Ra4 = (const float4*)Ria;
        float4* Out4 = (float4*)out;
        int vbase = g * (SEG / 4);
        #pragma unroll
        for (int j = 0; j < SEG / 4; j++) {
            float4 ft = To4[vbase + j], fi = Ir4[vbase + j], fq = Qi4[vbase + j];
            float4 fa = Qa4[vbase + j], fr = Ra4[vbase + j];
            // 4 maps computed in parallel (divisions out of the chain)
            Aff m0 = elem_map(c, ft.x, fi.x, fq.x, fa.x, fr.x);
            Aff m1 = elem_map(c, ft.y, fi.y, fq.y, fa.y, fr.y);
            Aff m2 = elem_map(c, ft.z, fi.z, fq.z, fa.z, fr.z);
            Aff m3 = elem_map(c, ft.w, fi.w, fq.w, fa.w, fr.w);
            // chain: x = A x + b  (2 dependent FFMAs per element)
            float ov[4];
            float t0, t1;
            t0 = m0.a11 * x0 + m0.a12 * x1 + m0.b0;
            t1 = m0.a21 * x0 + m0.a22 * x1 + m0.b1;
            x0 = t0; x1 = t1; ov[0] = x1;
            t0 = m1.a11 * x0 + m1.a12 * x1 + m1.b0;
            t1 = m1.a21 * x0 + m1.a22 * x1 + m1.b1;
            x0 = t0; x1 = t1; ov[1] = x1;
            t0 = m2.a11 * x0 + m2.a12 * x1 + m2.b0;
            t1 = m2.a21 * x0 + m2.a22 * x1 + m2.b1;
            x0 = t0; x1 = t1; ov[2] = x1;
            t0 = m3.a11 * x0 + m3.a12 * x1 + m3.b0;
            t1 = m3.a21 * x0 + m3.a22 * x1 + m3.b1;
            x0 = t0; x1 = t1; ov[3] = x1;
            Out4[vbase + j] = make_float4(ov[0], ov[1], ov[2], ov[3]);
        }
    } else if (base < (long)N) {
        for (long k = base; k < (long)N && k < base + SEG; k++) {
            Aff m = elem_map(c, To[k], Irr[k], Qint[k], Qah[k], Ria[k]);
            float t0 = m.a11 * x0 + m.a12 * x1 + m.b0;
            float t1 = m.a21 * x0 + m.a22 * x1 + m.b1;
            x0 = t0; x1 = t1;
            out[k] = x1;
        }
    }
}

extern "C" void kernel_launch(void* const* d_in, const int* in_sizes, int n_in,
                              void* d_out, int out_size)
{
    const float* R_ie    = (const float*)d_in[0];
    const float* R_ea    = (const float*)d_in[1];
    const float* C_in    = (const float*)d_in[2];
    const float* C_en    = (const float*)d_in[3];
    const float* a_sol_in = (const float*)d_in[4];
    const float* a_sol_en = (const float*)d_in[5];
    const float* a_int_in = (const float*)d_in[6];
    const float* a_int_en = (const float*)d_in[7];
    const float* Tin0    = (const float*)d_in[8];
    const float* To      = (const float*)d_in[9];
    const float* Irr     = (const float*)d_in[10];
    const float* Qint    = (const float*)d_in[11];
    const float* Qah     = (const float*)d_in[12];
    const float* Ria     = (const float*)d_in[13];
    float* out = (float*)d_out;

    int N = in_sizes[9];
    if (N <= 0) return;
    int nblk = (N + EPB - 1) / EPB;

    k1_segmaps<<<nblk, TPB>>>(To, Irr, Qint, Qah, Ria,
                              R_ie, R_ea, C_in, C_en,
                              a_sol_in, a_sol_en, a_int_in, a_int_en, N);
    k2_blockscan<<<1, K2_T>>>(Tin0, nblk);
    k3_replay<<<nblk, TPB>>>(To, Irr, Qint, Qah, Ria,
                             R_ie, R_ea, C_in, C_en,
                             a_sol_in, a_sol_en, a_int_in, a_int_en, out, N);
}